// round 16
// baseline (speedup 1.0000x reference)
#include <cuda_runtime.h>
#include <cuda_bf16.h>
#include <math.h>
#include <stdint.h>

#define MAXN 50000
#define MAXE 150000
#define DIN  128
#define H1   8
#define C1   128
#define F1   (H1*C1)    // 1024
#define DOUT 128

// ---------------------------------------------------------------------------
// Scratch
// ---------------------------------------------------------------------------
__device__ float g_h1   [(size_t)MAXN * F1];
__device__ float g_agg  [(size_t)MAXN * F1];
__device__ float g_h2   [(size_t)MAXN * DOUT];
__device__ float g_ssrc [(size_t)MAXN * H1];
__device__ float g_sdst [(size_t)MAXN * H1];
__device__ float g_ssrc2[(size_t)MAXN];
__device__ float g_sdst2[(size_t)MAXN];
__device__ float g_sum  [F1];
__device__ float g_sumsq[F1];
__device__ float g_mu   [F1];
__device__ float g_rstd [F1];
__device__ int   g_deg     [MAXN];
__device__ int   g_rowstart[MAXN + 1];
__device__ int   g_cursor  [MAXN];
__device__ int   g_csrc    [MAXE];
__device__ int   g_blocksum[256];
__device__ int   g_blockoff[256];

__device__ __forceinline__ float leaky(float x) { return x > 0.0f ? x : 0.2f * x; }

__device__ __forceinline__ uint32_t pack_bf16(float a, float b) {
    __nv_bfloat162 t = __floats2bfloat162_rn(a, b);
    return *reinterpret_cast<uint32_t*>(&t);
}
__device__ __forceinline__ void split_bf16(float f, float& hi, float& lo) {
    __nv_bfloat16 h = __float2bfloat16(f);
    hi = __bfloat162float(h);
    lo = f - hi;
}
__device__ __forceinline__ uint2 split_pair2(float a, float b) {
    float ha, la, hb, lb;
    split_bf16(a, ha, la);
    split_bf16(b, hb, lb);
    return make_uint2(pack_bf16(ha, hb), pack_bf16(la, lb));
}

// ---------------------------------------------------------------------------
// CSR build (parallel scan)
// ---------------------------------------------------------------------------
__global__ void init_kernel(int* deg, float* bsum, float* bsumsq, int N) {
    int i = blockIdx.x * blockDim.x + threadIdx.x;
    if (i < N) deg[i] = 0;
    if (i < F1) { bsum[i] = 0.0f; bsumsq[i] = 0.0f; }
}

__global__ void count_kernel(const int* __restrict__ ei, int* __restrict__ deg,
                             int E) {
    int e = blockIdx.x * blockDim.x + threadIdx.x;
    if (e < E) atomicAdd(&deg[ei[E + e]], 1);
}

__global__ __launch_bounds__(256)
void deg_partial_kernel(const int* __restrict__ deg, int* __restrict__ blocksum,
                        int N) {
    int i = blockIdx.x * 256 + threadIdx.x;
    int v = (i < N) ? deg[i] : 0;
    int lane = threadIdx.x & 31, w = threadIdx.x >> 5;
#pragma unroll
    for (int o = 16; o > 0; o >>= 1) v += __shfl_down_sync(0xffffffffu, v, o);
    __shared__ int ws[8];
    if (lane == 0) ws[w] = v;
    __syncthreads();
    if (threadIdx.x < 8) {
        int x = ws[threadIdx.x];
#pragma unroll
        for (int o = 4; o > 0; o >>= 1) x += __shfl_down_sync(0xffu, x, o, 8);
        if (threadIdx.x == 0) blocksum[blockIdx.x] = x;
    }
}

__global__ __launch_bounds__(256)
void scan_offsets_kernel(const int* __restrict__ blocksum,
                         int* __restrict__ blockoff, int nb) {
    int t = threadIdx.x;
    int v = (t < nb) ? blocksum[t] : 0;
    int lane = t & 31, w = t >> 5;
    int inc = v;
#pragma unroll
    for (int o = 1; o < 32; o <<= 1) {
        int u = __shfl_up_sync(0xffffffffu, inc, o);
        if (lane >= o) inc += u;
    }
    __shared__ int ws[8];
    if (lane == 31) ws[w] = inc;
    __syncthreads();
    if (t < 8) {
        int x = ws[t];
#pragma unroll
        for (int o = 1; o < 8; o <<= 1) {
            int u = __shfl_up_sync(0xffu, x, o, 8);
            if (t >= o) x += u;
        }
        ws[t] = x;
    }
    __syncthreads();
    int excl = inc - v + (w > 0 ? ws[w - 1] : 0);
    if (t < nb) blockoff[t] = excl;
}

__global__ __launch_bounds__(256)
void scan_write_kernel(const int* __restrict__ deg,
                       const int* __restrict__ blockoff,
                       int* __restrict__ rowstart, int* __restrict__ cursor,
                       int N) {
    int b = blockIdx.x, t = threadIdx.x;
    int i = b * 256 + t;
    int d = (i < N) ? deg[i] : 0;
    int lane = t & 31, w = t >> 5;
    int inc = d;
#pragma unroll
    for (int o = 1; o < 32; o <<= 1) {
        int u = __shfl_up_sync(0xffffffffu, inc, o);
        if (lane >= o) inc += u;
    }
    __shared__ int ws[8];
    if (lane == 31) ws[w] = inc;
    __syncthreads();
    if (t < 8) {
        int x = ws[t];
#pragma unroll
        for (int o = 1; o < 8; o <<= 1) {
            int u = __shfl_up_sync(0xffu, x, o, 8);
            if (t >= o) x += u;
        }
        ws[t] = x;
    }
    __syncthreads();
    int base = blockoff[b] + inc - d + (w > 0 ? ws[w - 1] : 0);
    if (i < N) { rowstart[i] = base; cursor[i] = base; }
    if (i == N - 1) rowstart[N] = base + d;
}

__global__ void scatter_kernel(const int* __restrict__ ei,
                               int* __restrict__ cursor,
                               int* __restrict__ csrc, int E) {
    int e = blockIdx.x * blockDim.x + threadIdx.x;
    if (e >= E) return;
    int d = ei[E + e];
    int pos = atomicAdd(&cursor[d], 1);
    csrc[pos] = ei[e];
}

// ---------------------------------------------------------------------------
// bf16x3 GEMM (error-compensated): C = A@B, fp32 in/out.
// Templated BMT (128 or 64) x BN=128, BK=16, 8 warps, mma.m16n8k16.bf16.
// Fused attention-score epilogue; BN_ELU=1 applies BN+ELU to A loads.
// ---------------------------------------------------------------------------
__device__ __forceinline__ void mma16(float* c, const uint32_t* a,
                                      const uint32_t* b) {
    asm volatile(
        "mma.sync.aligned.m16n8k16.row.col.f32.bf16.bf16.f32 "
        "{%0,%1,%2,%3}, {%4,%5,%6,%7}, {%8,%9}, {%0,%1,%2,%3};"
        : "+f"(c[0]), "+f"(c[1]), "+f"(c[2]), "+f"(c[3])
        : "r"(a[0]), "r"(a[1]), "r"(a[2]), "r"(a[3]),
          "r"(b[0]), "r"(b[1]));
}

#define KP  8
#define PAD 4

template <int BMT, int BN_ELU>
__global__ __launch_bounds__(256)
void bf16_gemm_kernel(const float* __restrict__ A,
                      const float* __restrict__ B,
                      float* __restrict__ C,
                      int M, int K, int N, int H,
                      const float* __restrict__ a_src,
                      const float* __restrict__ a_dst,
                      float* __restrict__ s_src,
                      float* __restrict__ s_dst,
                      const float* __restrict__ gamma,
                      const float* __restrict__ beta,
                      const float* __restrict__ mu,
                      const float* __restrict__ rstd) {
    const int BN = 128;
    const int MT = BMT / 32;
    __shared__ uint2 Ap[KP][BMT + PAD];
    __shared__ uint2 Bp[KP][BN + PAD];
    __shared__ float s_as[BN], s_ad[BN];
    __shared__ float red_s[BMT], red_d[BMT];

    const int tid  = threadIdx.x;
    const int wid  = tid >> 5;
    const int lane = tid & 31;
    const int bm = blockIdx.y * BMT;
    const int bn = blockIdx.x * BN;
    const int hd = bn >> 7;
    const int wm = (wid >> 2) * (BMT / 2);
    const int wn = (wid & 3) * 32;
    const int lg = lane >> 2;
    const int lt = lane & 3;

    if (tid < BN) {
        s_as[tid] = a_src[bn + tid];
        s_ad[tid] = a_dst[bn + tid];
    }
    if (tid < BMT) { red_s[tid] = 0.0f; red_d[tid] = 0.0f; }

    float acc[MT][4][4];
#pragma unroll
    for (int mt = 0; mt < MT; mt++)
#pragma unroll
        for (int nt = 0; nt < 4; nt++)
#pragma unroll
            for (int r = 0; r < 4; r++) acc[mt][nt][r] = 0.0f;

    for (int k0 = 0; k0 < K; k0 += 16) {
#pragma unroll
        for (int i = 0; i < BMT / 64; i++) {
            int lin = tid + i * 256;
            int r   = lin >> 2;
            int kb  = (lin & 3) << 2;
            int gr  = bm + r;
            float4 v = make_float4(0.f, 0.f, 0.f, 0.f);
            if (gr < M) {
                v = *(const float4*)&A[(size_t)gr * K + k0 + kb];
                if (BN_ELU) {
                    float vv[4] = {v.x, v.y, v.z, v.w};
#pragma unroll
                    for (int j = 0; j < 4; j++) {
                        int c = k0 + kb + j;
                        float t = gamma[c] * (vv[j] - mu[c]) * rstd[c] + beta[c];
                        vv[j] = t > 0.0f ? t : expm1f(t);
                    }
                    v = make_float4(vv[0], vv[1], vv[2], vv[3]);
                }
            }
            Ap[(kb >> 1)    ][r] = split_pair2(v.x, v.y);
            Ap[(kb >> 1) + 1][r] = split_pair2(v.z, v.w);
        }
        {
            int kp = tid >> 5;
            int c4 = (tid & 31) << 2;
            float4 b0 = *(const float4*)&B[(size_t)(k0 + 2 * kp) * N + bn + c4];
            float4 b1 = *(const float4*)&B[(size_t)(k0 + 2 * kp + 1) * N + bn + c4];
            float h0, l0, h1, l1;
            split_bf16(b0.x, h0, l0); split_bf16(b1.x, h1, l1);
            Bp[kp][c4 + 0] = make_uint2(pack_bf16(h0, h1), pack_bf16(l0, l1));
            split_bf16(b0.y, h0, l0); split_bf16(b1.y, h1, l1);
            Bp[kp][c4 + 1] = make_uint2(pack_bf16(h0, h1), pack_bf16(l0, l1));
            split_bf16(b0.z, h0, l0); split_bf16(b1.z, h1, l1);
            Bp[kp][c4 + 2] = make_uint2(pack_bf16(h0, h1), pack_bf16(l0, l1));
            split_bf16(b0.w, h0, l0); split_bf16(b1.w, h1, l1);
            Bp[kp][c4 + 3] = make_uint2(pack_bf16(h0, h1), pack_bf16(l0, l1));
        }
        __syncthreads();

        uint32_t ah[MT][4], al[MT][4];
#pragma unroll
        for (int mt = 0; mt < MT; mt++) {
            int r0 = wm + mt * 16 + lg;
            uint2 t0 = Ap[lt][r0];
            uint2 t1 = Ap[lt][r0 + 8];
            uint2 t2 = Ap[lt + 4][r0];
            uint2 t3 = Ap[lt + 4][r0 + 8];
            ah[mt][0] = t0.x; al[mt][0] = t0.y;
            ah[mt][1] = t1.x; al[mt][1] = t1.y;
            ah[mt][2] = t2.x; al[mt][2] = t2.y;
            ah[mt][3] = t3.x; al[mt][3] = t3.y;
        }
        uint32_t bh[4][2], bl[4][2];
#pragma unroll
        for (int nt = 0; nt < 4; nt++) {
            int cc = wn + nt * 8 + lg;
            uint2 u0 = Bp[lt][cc];
            uint2 u1 = Bp[lt + 4][cc];
            bh[nt][0] = u0.x; bl[nt][0] = u0.y;
            bh[nt][1] = u1.x; bl[nt][1] = u1.y;
        }
#pragma unroll
        for (int mt = 0; mt < MT; mt++)
#pragma unroll
            for (int nt = 0; nt < 4; nt++) {
                mma16(acc[mt][nt], ah[mt], bh[nt]);
                mma16(acc[mt][nt], ah[mt], bl[nt]);
                mma16(acc[mt][nt], al[mt], bh[nt]);
            }
        __syncthreads();
    }

#pragma unroll
    for (int mt = 0; mt < MT; mt++) {
#pragma unroll
        for (int half = 0; half < 2; half++) {
            int rl = wm + mt * 16 + lg + half * 8;
            int gr = bm + rl;
            float ps = 0.0f, pd = 0.0f;
#pragma unroll
            for (int nt = 0; nt < 4; nt++) {
                int cl = wn + nt * 8 + lt * 2;
                float v0 = acc[mt][nt][half * 2];
                float v1 = acc[mt][nt][half * 2 + 1];
                ps += v0 * s_as[cl] + v1 * s_as[cl + 1];
                pd += v0 * s_ad[cl] + v1 * s_ad[cl + 1];
                if (gr < M) {
                    *(float2*)&C[(size_t)gr * N + bn + cl] = make_float2(v0, v1);
                }
            }
            ps += __shfl_xor_sync(0xffffffffu, ps, 1);
            ps += __shfl_xor_sync(0xffffffffu, ps, 2);
            pd += __shfl_xor_sync(0xffffffffu, pd, 1);
            pd += __shfl_xor_sync(0xffffffffu, pd, 2);
            if (lt == 0) {
                atomicAdd(&red_s[rl], ps);
                atomicAdd(&red_d[rl], pd);
            }
        }
    }
    __syncthreads();
    if (tid < BMT && bm + tid < M) {
        s_src[(size_t)(bm + tid) * H + hd] = red_s[tid];
        s_dst[(size_t)(bm + tid) * H + hd] = red_d[tid];
    }
}

// ---------------------------------------------------------------------------
// Gather aggregation: register-cached edges + 4-way batched row loads (MLP=4)
// ---------------------------------------------------------------------------
__global__ __launch_bounds__(256)
void gather_agg1_kernel(const int* __restrict__ rowstart,
                        const int* __restrict__ csrc,
                        const float* __restrict__ ssrc,
                        const float* __restrict__ sdst,
                        const float* __restrict__ h,
                        float* __restrict__ agg, int N) {
    int n = blockIdx.x;
    if (n >= N) return;
    int hd = threadIdx.x >> 5;
    int lane = threadIdx.x & 31;
    int r0 = rowstart[n], r1 = rowstart[n + 1];
    int deg = r1 - r0;
    float sd = sdst[n * H1 + hd];

    float4 acc = make_float4(0.f, 0.f, 0.f, 0.f);
    float den = 0.0f;

    if (deg <= 32) {
        // pass 1: lane j caches edge j's (src, score)
        int s = -1;
        float v = -INFINITY;
        if (lane < deg) {
            s = csrc[r0 + lane];
            v = leaky(ssrc[s * H1 + hd] + sd);
        }
        float vmax = v;
#pragma unroll
        for (int o = 16; o > 0; o >>= 1)
            vmax = fmaxf(vmax, __shfl_xor_sync(0xffffffffu, vmax, o));

        // pass 2: 4-way batched (loads grouped before FMAs -> MLP=4)
        for (int j0 = 0; j0 < deg; j0 += 4) {
            int m = deg - j0;
            int   sj[4];
            float wj[4];
            float4 hv[4];
#pragma unroll
            for (int t = 0; t < 4; t++) {
                sj[t] = __shfl_sync(0xffffffffu, s, (j0 + t) & 31);
                float vt = __shfl_sync(0xffffffffu, v, (j0 + t) & 31);
                wj[t] = expf(vt - vmax);
            }
#pragma unroll
            for (int t = 0; t < 4; t++)
                if (t < m)
                    hv[t] = ((const float4*)(h + (size_t)sj[t] * F1 + hd * C1))[lane];
#pragma unroll
            for (int t = 0; t < 4; t++)
                if (t < m) {
                    den += wj[t];
                    acc.x += wj[t] * hv[t].x;
                    acc.y += wj[t] * hv[t].y;
                    acc.z += wj[t] * hv[t].z;
                    acc.w += wj[t] * hv[t].w;
                }
        }
    } else {
        // fallback: original two-pass loop (deg > 32; effectively never)
        float vmax = -INFINITY;
        for (int j = r0 + lane; j < r1; j += 32) {
            int s = csrc[j];
            vmax = fmaxf(vmax, leaky(ssrc[s * H1 + hd] + sd));
        }
#pragma unroll
        for (int o = 16; o > 0; o >>= 1)
            vmax = fmaxf(vmax, __shfl_xor_sync(0xffffffffu, vmax, o));
        for (int j = r0; j < r1; j++) {
            int s = csrc[j];
            float v = leaky(ssrc[s * H1 + hd] + sd);
            float w = expf(v - vmax);
            den += w;
            float4 hv = ((const float4*)(h + (size_t)s * F1 + hd * C1))[lane];
            acc.x += w * hv.x; acc.y += w * hv.y;
            acc.z += w * hv.z; acc.w += w * hv.w;
        }
    }

    float inv = 1.0f / (den + 1e-16f);
    float4* ap4 = (float4*)(agg + (size_t)n * F1 + hd * C1);
    ap4[lane] = make_float4(acc.x * inv, acc.y * inv, acc.z * inv, acc.w * inv);
}

__global__ void gather_out2_kernel(const int* __restrict__ rowstart,
                                   const int* __restrict__ csrc,
                                   const float* __restrict__ ssrc,
                                   const float* __restrict__ sdst,
                                   const float* __restrict__ h,
                                   const float* __restrict__ b2,
                                   float* __restrict__ out, int N) {
    int n = (blockIdx.x * blockDim.x + threadIdx.x) >> 5;
    int lane = threadIdx.x & 31;
    if (n >= N) return;
    int r0 = rowstart[n], r1 = rowstart[n + 1];
    int deg = r1 - r0;
    float sd = sdst[n];

    float4 acc = make_float4(0.f, 0.f, 0.f, 0.f);
    float den = 0.0f;

    if (deg <= 32) {
        int s = -1;
        float v = -INFINITY;
        if (lane < deg) {
            s = csrc[r0 + lane];
            v = leaky(ssrc[s] + sd);
        }
        float vmax = v;
#pragma unroll
        for (int o = 16; o > 0; o >>= 1)
            vmax = fmaxf(vmax, __shfl_xor_sync(0xffffffffu, vmax, o));

        for (int j0 = 0; j0 < deg; j0 += 4) {
            int m = deg - j0;
            int   sj[4];
            float wj[4];
            float4 hv[4];
#pragma unroll
            for (int t = 0; t < 4; t++) {
                sj[t] = __shfl_sync(0xffffffffu, s, (j0 + t) & 31);
                float vt = __shfl_sync(0xffffffffu, v, (j0 + t) & 31);
                wj[t] = expf(vt - vmax);
            }
#pragma unroll
            for (int t = 0; t < 4; t++)
                if (t < m)
                    hv[t] = ((const float4*)(h + (size_t)sj[t] * DOUT))[lane];
#pragma unroll
            for (int t = 0; t < 4; t++)
                if (t < m) {
                    den += wj[t];
                    acc.x += wj[t] * hv[t].x;
                    acc.y += wj[t] * hv[t].y;
                    acc.z += wj[t] * hv[t].z;
                    acc.w += wj[t] * hv[t].w;
                }
        }
    } else {
        float vmax = -INFINITY;
        for (int j = r0 + lane; j < r1; j += 32) {
            int s = csrc[j];
            vmax = fmaxf(vmax, leaky(ssrc[s] + sd));
        }
#pragma unroll
        for (int o = 16; o > 0; o >>= 1)
            vmax = fmaxf(vmax, __shfl_xor_sync(0xffffffffu, vmax, o));
        for (int j = r0; j < r1; j++) {
            int s = csrc[j];
            float v = leaky(ssrc[s] + sd);
            float w = expf(v - vmax);
            den += w;
            float4 hv = ((const float4*)(h + (size_t)s * DOUT))[lane];
            acc.x += w * hv.x; acc.y += w * hv.y;
            acc.z += w * hv.z; acc.w += w * hv.w;
        }
    }

    float inv = 1.0f / (den + 1e-16f);
    float4 bb = ((const float4*)b2)[lane];
    float4* op4 = (float4*)(out + (size_t)n * DOUT);
    op4[lane] = make_float4(acc.x * inv + bb.x, acc.y * inv + bb.y,
                            acc.z * inv + bb.z, acc.w * inv + bb.w);
}

// ---------------------------------------------------------------------------
// BN stats (b1 cancels in BatchNorm)
// ---------------------------------------------------------------------------
__global__ void bn_stats_kernel(const float* __restrict__ agg, int N) {
    int t = threadIdx.x;
    int c = t * 4;
    int rows_per_block = (N + gridDim.x - 1) / gridDim.x;
    int r0 = blockIdx.x * rows_per_block;
    int r1 = min(N, r0 + rows_per_block);
    float4 s = make_float4(0, 0, 0, 0);
    float4 q = make_float4(0, 0, 0, 0);
    for (int r = r0; r < r1; r++) {
        float4 v = ((const float4*)(agg + (size_t)r * F1))[t];
        s.x += v.x; s.y += v.y; s.z += v.z; s.w += v.w;
        q.x += v.x * v.x; q.y += v.y * v.y; q.z += v.z * v.z; q.w += v.w * v.w;
    }
    atomicAdd(&g_sum[c + 0], s.x); atomicAdd(&g_sum[c + 1], s.y);
    atomicAdd(&g_sum[c + 2], s.z); atomicAdd(&g_sum[c + 3], s.w);
    atomicAdd(&g_sumsq[c + 0], q.x); atomicAdd(&g_sumsq[c + 1], q.y);
    atomicAdd(&g_sumsq[c + 2], q.z); atomicAdd(&g_sumsq[c + 3], q.w);
}

__global__ void bn_finalize_kernel(int N) {
    int c = blockIdx.x * blockDim.x + threadIdx.x;
    if (c >= F1) return;
    float mu = g_sum[c] / (float)N;
    float var = g_sumsq[c] / (float)N - mu * mu;
    g_mu[c] = mu;
    g_rstd[c] = rsqrtf(var + 1e-5f);
}

// ---------------------------------------------------------------------------
static inline int cdiv(int a, int b) { return (a + b - 1) / b; }

extern "C" void kernel_launch(void* const* d_in, const int* in_sizes, int n_in,
                              void* d_out, int out_size) {
    const float* x = nullptr;
    const int* ei = nullptr;
    const float* W1 = nullptr; const float* W2 = nullptr;
    const float* v1024[5] = {nullptr, nullptr, nullptr, nullptr, nullptr};
    const float* v128[3]  = {nullptr, nullptr, nullptr};
    int n1024 = 0, n128 = 0, nW = 0;
    int N = MAXN, E = MAXE;

    for (int i = 0; i < n_in; i++) {
        int sz = in_sizes[i];
        if (sz == MAXN * DIN)          { x = (const float*)d_in[i]; N = sz / DIN; }
        else if (sz == 2 * MAXE)       { ei = (const int*)d_in[i]; E = sz / 2; }
        else if (sz == DIN * F1)       { if (nW == 0) W1 = (const float*)d_in[i];
                                         else W2 = (const float*)d_in[i]; nW++; }
        else if (sz == F1 && n1024 < 5) v1024[n1024++] = (const float*)d_in[i];
        else if (sz == DOUT && n128 < 3) v128[n128++] = (const float*)d_in[i];
    }
    const float* a_src1 = v1024[0];
    const float* a_dst1 = v1024[1];
    const float* gamma  = v1024[3];
    const float* beta   = v1024[4];
    const float* a_src2 = v128[0];
    const float* a_dst2 = v128[1];
    const float* b2     = v128[2];
    float* out = (float*)d_out;

    float *h1, *agg, *h2, *ssrc, *sdst, *ssrc2, *sdst2, *bsum, *bsumsq,
          *mu, *rstd;
    int *deg, *rowstart, *cursor, *csrc, *blocksum, *blockoff;
    cudaGetSymbolAddress((void**)&h1, g_h1);
    cudaGetSymbolAddress((void**)&agg, g_agg);
    cudaGetSymbolAddress((void**)&h2, g_h2);
    cudaGetSymbolAddress((void**)&ssrc, g_ssrc);
    cudaGetSymbolAddress((void**)&sdst, g_sdst);
    cudaGetSymbolAddress((void**)&ssrc2, g_ssrc2);
    cudaGetSymbolAddress((void**)&sdst2, g_sdst2);
    cudaGetSymbolAddress((void**)&bsum, g_sum);
    cudaGetSymbolAddress((void**)&bsumsq, g_sumsq);
    cudaGetSymbolAddress((void**)&mu, g_mu);
    cudaGetSymbolAddress((void**)&rstd, g_rstd);
    cudaGetSymbolAddress((void**)&deg, g_deg);
    cudaGetSymbolAddress((void**)&rowstart, g_rowstart);
    cudaGetSymbolAddress((void**)&cursor, g_cursor);
    cudaGetSymbolAddress((void**)&csrc, g_csrc);
    cudaGetSymbolAddress((void**)&blocksum, g_blocksum);
    cudaGetSymbolAddress((void**)&blockoff, g_blockoff);

    const int T = 256;
    const int NB = cdiv(N, 256);

    // 0-2: CSR prep
    init_kernel<<<cdiv(N, T), T>>>(deg, bsum, bsumsq, N);
    count_kernel<<<cdiv(E, T), T>>>(ei, deg, E);
    deg_partial_kernel<<<NB, 256>>>(deg, blocksum, N);
    // 3: GEMM1 (BM=128) + fused scores1  <-- profiled launch (control)
    {
        dim3 grid(F1 / 128, cdiv(N, 128));
        bf16_gemm_kernel<128, 0><<<grid, 256>>>(x, W1, h1, N, DIN, F1, H1,
                                                a_src1, a_dst1, ssrc, sdst,
                                                nullptr, nullptr, nullptr,
                                                nullptr);
    }
    // 4-6: finish CSR
    scan_offsets_kernel<<<1, 256>>>(blocksum, blockoff, NB);
    scan_write_kernel<<<NB, 256>>>(deg, blockoff, rowstart, cursor, N);
    scatter_kernel<<<cdiv(E, T), T>>>(ei, cursor, csrc, E);
    // 7: gather aggregation (register-cached edges, MLP=4)
    gather_agg1_kernel<<<N, 256>>>(rowstart, csrc, ssrc, sdst, h1, agg, N);
    // 8,9: BN stats
    bn_stats_kernel<<<200, 256>>>(agg, N);
    bn_finalize_kernel<<<cdiv(F1, T), T>>>(N);
    // 10: GEMM2 (BM=64; BN+ELU + scores fused)
    {
        dim3 grid(DOUT / 128, cdiv(N, 64));
        bf16_gemm_kernel<64, 1><<<grid, 256>>>(agg, W2, h2, N, F1, DOUT, 1,
                                               a_src2, a_dst2, ssrc2, sdst2,
                                               gamma, beta, mu, rstd);
    }
    // 11: layer-2 gather -> final output
    gather_out2_kernel<<<cdiv(N * 32, T), T>>>(rowstart, csrc, ssrc2, sdst2,
                                               h2, b2, out, N);
}

// round 17
// speedup vs baseline: 1.0653x; 1.0653x over previous
#include <cuda_runtime.h>
#include <cuda_bf16.h>
#include <math.h>
#include <stdint.h>

#define MAXN 50000
#define MAXE 150000
#define DIN  128
#define H1   8
#define C1   128
#define F1   (H1*C1)    // 1024
#define DOUT 128

// ---------------------------------------------------------------------------
// Scratch
// ---------------------------------------------------------------------------
__device__ float g_h1   [(size_t)MAXN * F1];
__device__ float g_agg  [(size_t)MAXN * F1];
__device__ float g_h2   [(size_t)MAXN * DOUT];
__device__ float g_ssrc [(size_t)MAXN * H1];
__device__ float g_sdst [(size_t)MAXN * H1];
__device__ float g_ssrc2[(size_t)MAXN];
__device__ float g_sdst2[(size_t)MAXN];
__device__ float g_sum  [F1];
__device__ float g_sumsq[F1];
__device__ float g_mu   [F1];
__device__ float g_rstd [F1];
__device__ int   g_deg     [MAXN];
__device__ int   g_rowstart[MAXN + 1];
__device__ int   g_cursor  [MAXN];
__device__ int   g_csrc    [MAXE];
__device__ int   g_blocksum[256];
__device__ int   g_blockoff[256];

__device__ __forceinline__ float leaky(float x) { return x > 0.0f ? x : 0.2f * x; }

__device__ __forceinline__ uint32_t pack_bf16(float a, float b) {
    __nv_bfloat162 t = __floats2bfloat162_rn(a, b);
    return *reinterpret_cast<uint32_t*>(&t);
}
__device__ __forceinline__ void split_bf16(float f, float& hi, float& lo) {
    __nv_bfloat16 h = __float2bfloat16(f);
    hi = __bfloat162float(h);
    lo = f - hi;
}
__device__ __forceinline__ uint2 split_pair2(float a, float b) {
    float ha, la, hb, lb;
    split_bf16(a, ha, la);
    split_bf16(b, hb, lb);
    return make_uint2(pack_bf16(ha, hb), pack_bf16(la, lb));
}

// ---------------------------------------------------------------------------
// CSR build (parallel scan)
// ---------------------------------------------------------------------------
__global__ void init_kernel(int* deg, float* bsum, float* bsumsq, int N) {
    int i = blockIdx.x * blockDim.x + threadIdx.x;
    if (i < N) deg[i] = 0;
    if (i < F1) { bsum[i] = 0.0f; bsumsq[i] = 0.0f; }
}

__global__ void count_kernel(const int* __restrict__ ei, int* __restrict__ deg,
                             int E) {
    int e = blockIdx.x * blockDim.x + threadIdx.x;
    if (e < E) atomicAdd(&deg[ei[E + e]], 1);
}

__global__ __launch_bounds__(256)
void deg_partial_kernel(const int* __restrict__ deg, int* __restrict__ blocksum,
                        int N) {
    int i = blockIdx.x * 256 + threadIdx.x;
    int v = (i < N) ? deg[i] : 0;
    int lane = threadIdx.x & 31, w = threadIdx.x >> 5;
#pragma unroll
    for (int o = 16; o > 0; o >>= 1) v += __shfl_down_sync(0xffffffffu, v, o);
    __shared__ int ws[8];
    if (lane == 0) ws[w] = v;
    __syncthreads();
    if (threadIdx.x < 8) {
        int x = ws[threadIdx.x];
#pragma unroll
        for (int o = 4; o > 0; o >>= 1) x += __shfl_down_sync(0xffu, x, o, 8);
        if (threadIdx.x == 0) blocksum[blockIdx.x] = x;
    }
}

__global__ __launch_bounds__(256)
void scan_offsets_kernel(const int* __restrict__ blocksum,
                         int* __restrict__ blockoff, int nb) {
    int t = threadIdx.x;
    int v = (t < nb) ? blocksum[t] : 0;
    int lane = t & 31, w = t >> 5;
    int inc = v;
#pragma unroll
    for (int o = 1; o < 32; o <<= 1) {
        int u = __shfl_up_sync(0xffffffffu, inc, o);
        if (lane >= o) inc += u;
    }
    __shared__ int ws[8];
    if (lane == 31) ws[w] = inc;
    __syncthreads();
    if (t < 8) {
        int x = ws[t];
#pragma unroll
        for (int o = 1; o < 8; o <<= 1) {
            int u = __shfl_up_sync(0xffu, x, o, 8);
            if (t >= o) x += u;
        }
        ws[t] = x;
    }
    __syncthreads();
    int excl = inc - v + (w > 0 ? ws[w - 1] : 0);
    if (t < nb) blockoff[t] = excl;
}

__global__ __launch_bounds__(256)
void scan_write_kernel(const int* __restrict__ deg,
                       const int* __restrict__ blockoff,
                       int* __restrict__ rowstart, int* __restrict__ cursor,
                       int N) {
    int b = blockIdx.x, t = threadIdx.x;
    int i = b * 256 + t;
    int d = (i < N) ? deg[i] : 0;
    int lane = t & 31, w = t >> 5;
    int inc = d;
#pragma unroll
    for (int o = 1; o < 32; o <<= 1) {
        int u = __shfl_up_sync(0xffffffffu, inc, o);
        if (lane >= o) inc += u;
    }
    __shared__ int ws[8];
    if (lane == 31) ws[w] = inc;
    __syncthreads();
    if (t < 8) {
        int x = ws[t];
#pragma unroll
        for (int o = 1; o < 8; o <<= 1) {
            int u = __shfl_up_sync(0xffu, x, o, 8);
            if (t >= o) x += u;
        }
        ws[t] = x;
    }
    __syncthreads();
    int base = blockoff[b] + inc - d + (w > 0 ? ws[w - 1] : 0);
    if (i < N) { rowstart[i] = base; cursor[i] = base; }
    if (i == N - 1) rowstart[N] = base + d;
}

__global__ void scatter_kernel(const int* __restrict__ ei,
                               int* __restrict__ cursor,
                               int* __restrict__ csrc, int E) {
    int e = blockIdx.x * blockDim.x + threadIdx.x;
    if (e >= E) return;
    int d = ei[E + e];
    int pos = atomicAdd(&cursor[d], 1);
    csrc[pos] = ei[e];
}

// ---------------------------------------------------------------------------
// mma helper
// ---------------------------------------------------------------------------
__device__ __forceinline__ void mma16(float* c, const uint32_t* a,
                                      const uint32_t* b) {
    asm volatile(
        "mma.sync.aligned.m16n8k16.row.col.f32.bf16.bf16.f32 "
        "{%0,%1,%2,%3}, {%4,%5,%6,%7}, {%8,%9}, {%0,%1,%2,%3};"
        : "+f"(c[0]), "+f"(c[1]), "+f"(c[2]), "+f"(c[3])
        : "r"(a[0]), "r"(a[1]), "r"(a[2]), "r"(a[3]),
          "r"(b[0]), "r"(b[1]));
}

#define KP  8
#define PAD 4

// ---------------------------------------------------------------------------
// GEMM1: bf16x3, BM=128 x BN=128, single-buffer (R11/R15 verified).
// Fused scores epilogue.
// ---------------------------------------------------------------------------
__global__ __launch_bounds__(256)
void bf16_gemm1_kernel(const float* __restrict__ A,
                       const float* __restrict__ B,
                       float* __restrict__ C,
                       int M, int K, int N, int H,
                       const float* __restrict__ a_src,
                       const float* __restrict__ a_dst,
                       float* __restrict__ s_src,
                       float* __restrict__ s_dst) {
    const int BM = 128, BN = 128;
    __shared__ uint2 Ap[KP][BM + PAD];
    __shared__ uint2 Bp[KP][BN + PAD];
    __shared__ float s_as[BN], s_ad[BN];
    __shared__ float red_s[BM], red_d[BM];

    const int tid  = threadIdx.x;
    const int wid  = tid >> 5;
    const int lane = tid & 31;
    const int bm = blockIdx.y * BM;
    const int bn = blockIdx.x * BN;
    const int hd = bn >> 7;
    const int wm = (wid >> 2) * 64;
    const int wn = (wid & 3) * 32;
    const int lg = lane >> 2;
    const int lt = lane & 3;

    if (tid < BN) {
        s_as[tid] = a_src[bn + tid];
        s_ad[tid] = a_dst[bn + tid];
    }
    if (tid < BM) { red_s[tid] = 0.0f; red_d[tid] = 0.0f; }

    float acc[4][4][4];
#pragma unroll
    for (int mt = 0; mt < 4; mt++)
#pragma unroll
        for (int nt = 0; nt < 4; nt++)
#pragma unroll
            for (int r = 0; r < 4; r++) acc[mt][nt][r] = 0.0f;

    for (int k0 = 0; k0 < K; k0 += 16) {
#pragma unroll
        for (int i = 0; i < 2; i++) {
            int lin = tid + i * 256;
            int r   = lin >> 2;
            int kb  = (lin & 3) << 2;
            int gr  = bm + r;
            float4 v = make_float4(0.f, 0.f, 0.f, 0.f);
            if (gr < M) v = *(const float4*)&A[(size_t)gr * K + k0 + kb];
            Ap[(kb >> 1)    ][r] = split_pair2(v.x, v.y);
            Ap[(kb >> 1) + 1][r] = split_pair2(v.z, v.w);
        }
        {
            int kp = tid >> 5;
            int c4 = (tid & 31) << 2;
            float4 b0 = *(const float4*)&B[(size_t)(k0 + 2 * kp) * N + bn + c4];
            float4 b1 = *(const float4*)&B[(size_t)(k0 + 2 * kp + 1) * N + bn + c4];
            float h0, l0, h1, l1;
            split_bf16(b0.x, h0, l0); split_bf16(b1.x, h1, l1);
            Bp[kp][c4 + 0] = make_uint2(pack_bf16(h0, h1), pack_bf16(l0, l1));
            split_bf16(b0.y, h0, l0); split_bf16(b1.y, h1, l1);
            Bp[kp][c4 + 1] = make_uint2(pack_bf16(h0, h1), pack_bf16(l0, l1));
            split_bf16(b0.z, h0, l0); split_bf16(b1.z, h1, l1);
            Bp[kp][c4 + 2] = make_uint2(pack_bf16(h0, h1), pack_bf16(l0, l1));
            split_bf16(b0.w, h0, l0); split_bf16(b1.w, h1, l1);
            Bp[kp][c4 + 3] = make_uint2(pack_bf16(h0, h1), pack_bf16(l0, l1));
        }
        __syncthreads();

        uint32_t ah[4][4], al[4][4];
#pragma unroll
        for (int mt = 0; mt < 4; mt++) {
            int r0 = wm + mt * 16 + lg;
            uint2 t0 = Ap[lt][r0];
            uint2 t1 = Ap[lt][r0 + 8];
            uint2 t2 = Ap[lt + 4][r0];
            uint2 t3 = Ap[lt + 4][r0 + 8];
            ah[mt][0] = t0.x; al[mt][0] = t0.y;
            ah[mt][1] = t1.x; al[mt][1] = t1.y;
            ah[mt][2] = t2.x; al[mt][2] = t2.y;
            ah[mt][3] = t3.x; al[mt][3] = t3.y;
        }
        uint32_t bh[4][2], bl[4][2];
#pragma unroll
        for (int nt = 0; nt < 4; nt++) {
            int cc = wn + nt * 8 + lg;
            uint2 u0 = Bp[lt][cc];
            uint2 u1 = Bp[lt + 4][cc];
            bh[nt][0] = u0.x; bl[nt][0] = u0.y;
            bh[nt][1] = u1.x; bl[nt][1] = u1.y;
        }
#pragma unroll
        for (int mt = 0; mt < 4; mt++)
#pragma unroll
            for (int nt = 0; nt < 4; nt++) {
                mma16(acc[mt][nt], ah[mt], bh[nt]);
                mma16(acc[mt][nt], ah[mt], bl[nt]);
                mma16(acc[mt][nt], al[mt], bh[nt]);
            }
        __syncthreads();
    }

#pragma unroll
    for (int mt = 0; mt < 4; mt++) {
#pragma unroll
        for (int half = 0; half < 2; half++) {
            int rl = wm + mt * 16 + lg + half * 8;
            int gr = bm + rl;
            float ps = 0.0f, pd = 0.0f;
#pragma unroll
            for (int nt = 0; nt < 4; nt++) {
                int cl = wn + nt * 8 + lt * 2;
                float v0 = acc[mt][nt][half * 2];
                float v1 = acc[mt][nt][half * 2 + 1];
                ps += v0 * s_as[cl] + v1 * s_as[cl + 1];
                pd += v0 * s_ad[cl] + v1 * s_ad[cl + 1];
                if (gr < M) {
                    *(float2*)&C[(size_t)gr * N + bn + cl] = make_float2(v0, v1);
                }
            }
            ps += __shfl_xor_sync(0xffffffffu, ps, 1);
            ps += __shfl_xor_sync(0xffffffffu, ps, 2);
            pd += __shfl_xor_sync(0xffffffffu, pd, 1);
            pd += __shfl_xor_sync(0xffffffffu, pd, 2);
            if (lt == 0) {
                atomicAdd(&red_s[rl], ps);
                atomicAdd(&red_d[rl], pd);
            }
        }
    }
    __syncthreads();
    if (tid < BM && bm + tid < M) {
        s_src[(size_t)(bm + tid) * H + hd] = red_s[tid];
        s_dst[(size_t)(bm + tid) * H + hd] = red_d[tid];
    }
}

// ---------------------------------------------------------------------------
// GEMM2: bf16x3, BM=64 x BN=128, register-staged DOUBLE BUFFER (static smem,
// ~27KB -> 2 CTAs/SM preserved). BN+ELU fused on A; fused scores epilogue.
// Grid: (1, cdiv(M,64)); N = 128, bn = 0, hd = 0.
// ---------------------------------------------------------------------------
__global__ __launch_bounds__(256)
void bf16_gemm2_db_kernel(const float* __restrict__ A,
                          const float* __restrict__ B,
                          float* __restrict__ C,
                          int M, int K,
                          const float* __restrict__ a_src,
                          const float* __restrict__ a_dst,
                          float* __restrict__ s_src,
                          float* __restrict__ s_dst,
                          const float* __restrict__ gamma,
                          const float* __restrict__ beta,
                          const float* __restrict__ mu,
                          const float* __restrict__ rstd) {
    const int BMT = 64, BN = 128;
    __shared__ uint2 Ap[2][KP][BMT + PAD];
    __shared__ uint2 Bp[2][KP][BN + PAD];
    __shared__ float s_as[BN], s_ad[BN];
    __shared__ float red_s[BMT], red_d[BMT];

    const int tid  = threadIdx.x;
    const int wid  = tid >> 5;
    const int lane = tid & 31;
    const int bm = blockIdx.y * BMT;
    const int wm = (wid >> 2) * 32;
    const int wn = (wid & 3) * 32;
    const int lg = lane >> 2;
    const int lt = lane & 3;

    if (tid < BN) {
        s_as[tid] = a_src[tid];
        s_ad[tid] = a_dst[tid];
    }
    if (tid < BMT) { red_s[tid] = 0.0f; red_d[tid] = 0.0f; }

    float acc[2][4][4];
#pragma unroll
    for (int mt = 0; mt < 2; mt++)
#pragma unroll
        for (int nt = 0; nt < 4; nt++)
#pragma unroll
            for (int r = 0; r < 4; r++) acc[mt][nt][r] = 0.0f;

    // loader coords (fixed per thread)
    const int ar  = tid >> 2;            // A row 0..63
    const int akb = (tid & 3) << 2;      // A k offset 0,4,8,12
    const int bkp = tid >> 5;            // B kpair 0..7
    const int bc4 = (tid & 31) << 2;     // B col 0..124
    const int agr = bm + ar;

    float4 aReg, bReg0, bReg1;

    auto load_regs = [&](int k0) {
        float4 v = make_float4(0.f, 0.f, 0.f, 0.f);
        if (agr < M) {
            v = *(const float4*)&A[(size_t)agr * K + k0 + akb];
            float vv[4] = {v.x, v.y, v.z, v.w};
#pragma unroll
            for (int j = 0; j < 4; j++) {
                int c = k0 + akb + j;
                float t = gamma[c] * (vv[j] - mu[c]) * rstd[c] + beta[c];
                vv[j] = t > 0.0f ? t : expm1f(t);
            }
            v = make_float4(vv[0], vv[1], vv[2], vv[3]);
        }
        aReg = v;
        bReg0 = *(const float4*)&B[(size_t)(k0 + 2 * bkp) * BN + bc4];
        bReg1 = *(const float4*)&B[(size_t)(k0 + 2 * bkp + 1) * BN + bc4];
    };

    auto store_stage = [&](int st) {
        Ap[st][(akb >> 1)    ][ar] = split_pair2(aReg.x, aReg.y);
        Ap[st][(akb >> 1) + 1][ar] = split_pair2(aReg.z, aReg.w);
        float h0, l0, h1, l1;
        split_bf16(bReg0.x, h0, l0); split_bf16(bReg1.x, h1, l1);
        Bp[st][bkp][bc4 + 0] = make_uint2(pack_bf16(h0, h1), pack_bf16(l0, l1));
        split_bf16(bReg0.y, h0, l0); split_bf16(bReg1.y, h1, l1);
        Bp[st][bkp][bc4 + 1] = make_uint2(pack_bf16(h0, h1), pack_bf16(l0, l1));
        split_bf16(bReg0.z, h0, l0); split_bf16(bReg1.z, h1, l1);
        Bp[st][bkp][bc4 + 2] = make_uint2(pack_bf16(h0, h1), pack_bf16(l0, l1));
        split_bf16(bReg0.w, h0, l0); split_bf16(bReg1.w, h1, l1);
        Bp[st][bkp][bc4 + 3] = make_uint2(pack_bf16(h0, h1), pack_bf16(l0, l1));
    };

    auto mma_stage = [&](int st) {
        uint32_t ah[2][4], al[2][4];
#pragma unroll
        for (int mt = 0; mt < 2; mt++) {
            int r0 = wm + mt * 16 + lg;
            uint2 t0 = Ap[st][lt][r0];
            uint2 t1 = Ap[st][lt][r0 + 8];
            uint2 t2 = Ap[st][lt + 4][r0];
            uint2 t3 = Ap[st][lt + 4][r0 + 8];
            ah[mt][0] = t0.x; al[mt][0] = t0.y;
            ah[mt][1] = t1.x; al[mt][1] = t1.y;
            ah[mt][2] = t2.x; al[mt][2] = t2.y;
            ah[mt][3] = t3.x; al[mt][3] = t3.y;
        }
        uint32_t bh[4][2], bl[4][2];
#pragma unroll
        for (int nt = 0; nt < 4; nt++) {
            int cc = wn + nt * 8 + lg;
            uint2 u0 = Bp[st][lt][cc];
            uint2 u1 = Bp[st][lt + 4][cc];
            bh[nt][0] = u0.x; bl[nt][0] = u0.y;
            bh[nt][1] = u1.x; bl[nt][1] = u1.y;
        }
#pragma unroll
        for (int mt = 0; mt < 2; mt++)
#pragma unroll
            for (int nt = 0; nt < 4; nt++) {
                mma16(acc[mt][nt], ah[mt], bh[nt]);
                mma16(acc[mt][nt], ah[mt], bl[nt]);
                mma16(acc[mt][nt], al[mt], bh[nt]);
            }
    };

    load_regs(0);
    store_stage(0);
    __syncthreads();
    int cur = 0;
    for (int k0 = 0; k0 < K; k0 += 16) {
        bool nxt = (k0 + 16 < K);
        if (nxt) load_regs(k0 + 16);        // global loads overlap mma below
        mma_stage(cur);
        if (nxt) {
            store_stage(cur ^ 1);           // other stage: last read 2 iters ago
            __syncthreads();
            cur ^= 1;
        }
    }

    // epilogue
#pragma unroll
    for (int mt = 0; mt < 2; mt++) {
#pragma unroll
        for (int half = 0; half < 2; half++) {
            int rl = wm + mt * 16 + lg + half * 8;
            int gr = bm + rl;
            float ps = 0.0f, pd = 0.0f;
#pragma unroll
            for (int nt = 0; nt < 4; nt++) {
                int cl = wn + nt * 8 + lt * 2;
                float v0 = acc[mt][nt][half * 2];
                float v1 = acc[mt][nt][half * 2 + 1];
                ps += v0 * s_as[cl] + v1 * s_as[cl + 1];
                pd += v0 * s_ad[cl] + v1 * s_ad[cl + 1];
                if (gr < M) {
                    *(float2*)&C[(size_t)gr * BN + cl] = make_float2(v0, v1);
                }
            }
            ps += __shfl_xor_sync(0xffffffffu, ps, 1);
            ps += __shfl_xor_sync(0xffffffffu, ps, 2);
            pd += __shfl_xor_sync(0xffffffffu, pd, 1);
            pd += __shfl_xor_sync(0xffffffffu, pd, 2);
            if (lt == 0) {
                atomicAdd(&red_s[rl], ps);
                atomicAdd(&red_d[rl], pd);
            }
        }
    }
    __syncthreads();
    if (tid < BMT && bm + tid < M) {
        s_src[bm + tid] = red_s[tid];
        s_dst[bm + tid] = red_d[tid];
    }
}

// ---------------------------------------------------------------------------
// Gather aggregation (R15 best: plain float4 loop)
// ---------------------------------------------------------------------------
__global__ __launch_bounds__(256)
void gather_agg1_kernel(const int* __restrict__ rowstart,
                        const int* __restrict__ csrc,
                        const float* __restrict__ ssrc,
                        const float* __restrict__ sdst,
                        const float* __restrict__ h,
                        float* __restrict__ agg, int N) {
    int n = blockIdx.x;
    if (n >= N) return;
    int hd = threadIdx.x >> 5;
    int lane = threadIdx.x & 31;
    int r0 = rowstart[n], r1 = rowstart[n + 1];
    float sd = sdst[n * H1 + hd];

    float vmax = -INFINITY;
    for (int j = r0 + lane; j < r1; j += 32) {
        int s = csrc[j];
        vmax = fmaxf(vmax, leaky(ssrc[s * H1 + hd] + sd));
    }
#pragma unroll
    for (int o = 16; o > 0; o >>= 1)
        vmax = fmaxf(vmax, __shfl_xor_sync(0xffffffff, vmax, o));

    float4 acc = make_float4(0.f, 0.f, 0.f, 0.f);
    float den = 0.0f;
    for (int j = r0; j < r1; j++) {
        int s = csrc[j];
        float v = leaky(ssrc[s * H1 + hd] + sd);
        float w = expf(v - vmax);
        den += w;
        float4 hv = ((const float4*)(h + (size_t)s * F1 + hd * C1))[lane];
        acc.x += w * hv.x;
        acc.y += w * hv.y;
        acc.z += w * hv.z;
        acc.w += w * hv.w;
    }
    float inv = 1.0f / (den + 1e-16f);
    float4* ap4 = (float4*)(agg + (size_t)n * F1 + hd * C1);
    ap4[lane] = make_float4(acc.x * inv, acc.y * inv, acc.z * inv, acc.w * inv);
}

__global__ void gather_out2_kernel(const int* __restrict__ rowstart,
                                   const int* __restrict__ csrc,
                                   const float* __restrict__ ssrc,
                                   const float* __restrict__ sdst,
                                   const float* __restrict__ h,
                                   const float* __restrict__ b2,
                                   float* __restrict__ out, int N) {
    int n = (blockIdx.x * blockDim.x + threadIdx.x) >> 5;
    int lane = threadIdx.x & 31;
    if (n >= N) return;
    int r0 = rowstart[n], r1 = rowstart[n + 1];
    float sd = sdst[n];

    float vmax = -INFINITY;
    for (int j = r0 + lane; j < r1; j += 32) {
        int s = csrc[j];
        vmax = fmaxf(vmax, leaky(ssrc[s] + sd));
    }
#pragma unroll
    for (int o = 16; o > 0; o >>= 1)
        vmax = fmaxf(vmax, __shfl_xor_sync(0xffffffff, vmax, o));

    float4 acc = make_float4(0.f, 0.f, 0.f, 0.f);
    float den = 0.0f;
    for (int j = r0; j < r1; j++) {
        int s = csrc[j];
        float v = leaky(ssrc[s] + sd);
        float w = expf(v - vmax);
        den += w;
        float4 hv = ((const float4*)(h + (size_t)s * DOUT))[lane];
        acc.x += w * hv.x;
        acc.y += w * hv.y;
        acc.z += w * hv.z;
        acc.w += w * hv.w;
    }
    float inv = 1.0f / (den + 1e-16f);
    float4 bb = ((const float4*)b2)[lane];
    float4* op4 = (float4*)(out + (size_t)n * DOUT);
    op4[lane] = make_float4(acc.x * inv + bb.x, acc.y * inv + bb.y,
                            acc.z * inv + bb.z, acc.w * inv + bb.w);
}

// ---------------------------------------------------------------------------
// BN stats
// ---------------------------------------------------------------------------
__global__ void bn_stats_kernel(const float* __restrict__ agg, int N) {
    int t = threadIdx.x;
    int c = t * 4;
    int rows_per_block = (N + gridDim.x - 1) / gridDim.x;
    int r0 = blockIdx.x * rows_per_block;
    int r1 = min(N, r0 + rows_per_block);
    float4 s = make_float4(0, 0, 0, 0);
    float4 q = make_float4(0, 0, 0, 0);
    for (int r = r0; r < r1; r++) {
        float4 v = ((const float4*)(agg + (size_t)r * F1))[t];
        s.x += v.x; s.y += v.y; s.z += v.z; s.w += v.w;
        q.x += v.x * v.x; q.y += v.y * v.y; q.z += v.z * v.z; q.w += v.w * v.w;
    }
    atomicAdd(&g_sum[c + 0], s.x); atomicAdd(&g_sum[c + 1], s.y);
    atomicAdd(&g_sum[c + 2], s.z); atomicAdd(&g_sum[c + 3], s.w);
    atomicAdd(&g_sumsq[c + 0], q.x); atomicAdd(&g_sumsq[c + 1], q.y);
    atomicAdd(&g_sumsq[c + 2], q.z); atomicAdd(&g_sumsq[c + 3], q.w);
}

__global__ void bn_finalize_kernel(int N) {
    int c = blockIdx.x * blockDim.x + threadIdx.x;
    if (c >= F1) return;
    float mu = g_sum[c] / (float)N;
    float var = g_sumsq[c] / (float)N - mu * mu;
    g_mu[c] = mu;
    g_rstd[c] = rsqrtf(var + 1e-5f);
}

// ---------------------------------------------------------------------------
static inline int cdiv(int a, int b) { return (a + b - 1) / b; }

extern "C" void kernel_launch(void* const* d_in, const int* in_sizes, int n_in,
                              void* d_out, int out_size) {
    const float* x = nullptr;
    const int* ei = nullptr;
    const float* W1 = nullptr; const float* W2 = nullptr;
    const float* v1024[5] = {nullptr, nullptr, nullptr, nullptr, nullptr};
    const float* v128[3]  = {nullptr, nullptr, nullptr};
    int n1024 = 0, n128 = 0, nW = 0;
    int N = MAXN, E = MAXE;

    for (int i = 0; i < n_in; i++) {
        int sz = in_sizes[i];
        if (sz == MAXN * DIN)          { x = (const float*)d_in[i]; N = sz / DIN; }
        else if (sz == 2 * MAXE)       { ei = (const int*)d_in[i]; E = sz / 2; }
        else if (sz == DIN * F1)       { if (nW == 0) W1 = (const float*)d_in[i];
                                         else W2 = (const float*)d_in[i]; nW++; }
        else if (sz == F1 && n1024 < 5) v1024[n1024++] = (const float*)d_in[i];
        else if (sz == DOUT && n128 < 3) v128[n128++] = (const float*)d_in[i];
    }
    const float* a_src1 = v1024[0];
    const float* a_dst1 = v1024[1];
    const float* gamma  = v1024[3];
    const float* beta   = v1024[4];
    const float* a_src2 = v128[0];
    const float* a_dst2 = v128[1];
    const float* b2     = v128[2];
    float* out = (float*)d_out;

    float *h1, *agg, *h2, *ssrc, *sdst, *ssrc2, *sdst2, *bsum, *bsumsq,
          *mu, *rstd;
    int *deg, *rowstart, *cursor, *csrc, *blocksum, *blockoff;
    cudaGetSymbolAddress((void**)&h1, g_h1);
    cudaGetSymbolAddress((void**)&agg, g_agg);
    cudaGetSymbolAddress((void**)&h2, g_h2);
    cudaGetSymbolAddress((void**)&ssrc, g_ssrc);
    cudaGetSymbolAddress((void**)&sdst, g_sdst);
    cudaGetSymbolAddress((void**)&ssrc2, g_ssrc2);
    cudaGetSymbolAddress((void**)&sdst2, g_sdst2);
    cudaGetSymbolAddress((void**)&bsum, g_sum);
    cudaGetSymbolAddress((void**)&bsumsq, g_sumsq);
    cudaGetSymbolAddress((void**)&mu, g_mu);
    cudaGetSymbolAddress((void**)&rstd, g_rstd);
    cudaGetSymbolAddress((void**)&deg, g_deg);
    cudaGetSymbolAddress((void**)&rowstart, g_rowstart);
    cudaGetSymbolAddress((void**)&cursor, g_cursor);
    cudaGetSymbolAddress((void**)&csrc, g_csrc);
    cudaGetSymbolAddress((void**)&blocksum, g_blocksum);
    cudaGetSymbolAddress((void**)&blockoff, g_blockoff);

    const int T = 256;
    const int NB = cdiv(N, 256);

    // 0-2: CSR prep
    init_kernel<<<cdiv(N, T), T>>>(deg, bsum, bsumsq, N);
    count_kernel<<<cdiv(E, T), T>>>(ei, deg, E);
    deg_partial_kernel<<<NB, 256>>>(deg, blocksum, N);
    // 3: GEMM1 + fused scores1  <-- profiled launch (control)
    {
        dim3 grid(F1 / 128, cdiv(N, 128));
        bf16_gemm1_kernel<<<grid, 256>>>(x, W1, h1, N, DIN, F1, H1,
                                         a_src1, a_dst1, ssrc, sdst);
    }
    // 4-6: finish CSR
    scan_offsets_kernel<<<1, 256>>>(blocksum, blockoff, NB);
    scan_write_kernel<<<NB, 256>>>(deg, blockoff, rowstart, cursor, N);
    scatter_kernel<<<cdiv(E, T), T>>>(ei, cursor, csrc, E);
    // 7: gather aggregation
    gather_agg1_kernel<<<N, 256>>>(rowstart, csrc, ssrc, sdst, h1, agg, N);
    // 8,9: BN stats
    bn_stats_kernel<<<200, 256>>>(agg, N);
    bn_finalize_kernel<<<cdiv(F1, T), T>>>(N);
    // 10: GEMM2 double-buffered (BM=64; BN+ELU + scores fused)
    {
        dim3 grid(1, cdiv(N, 64));
        bf16_gemm2_db_kernel<<<grid, 256>>>(agg, W2, h2, N, F1,
                                            a_src2, a_dst2, ssrc2, sdst2,
                                            gamma, beta, mu, rstd);
    }
    // 11: layer-2 gather -> final output
    gather_out2_kernel<<<cdiv(N * 32, T), T>>>(rowstart, csrc, ssrc2, sdst2,
                                               h2, b2, out, N);
}